// round 17
// baseline (speedup 1.0000x reference)
#include <cuda_runtime.h>
#include <cuda_bf16.h>
#include <cstdint>

#define NB 256          // cells in minibatch
#define NG 2000         // genes_oi
#define NL 64           // latent dim
#define NC 128          // spline bins
#define NCUTS_C 500000
#define LOG_NBINS 4.852030263919617f   // ln(128)
#define LOG2E 1.4426950408889634f
#define LN2 0.6931471805599453f
#define NBUCKET (NG * 2)               // (gene, half) buckets
#define CAP 320                        // fixed bucket capacity (mean 125, max ~172)

#define LAT_BLOCKS 8
#define CUT_PAIRS (NCUTS_C / 2)
#define CUT_BLOCKS ((CUT_PAIRS + 255) / 256)

#define NBLK 296                       // persistent gemm blocks (2/SM x 148)
#define LDA 72                         // Asm row stride, bf16
#define LDSTG 132                      // f32 stage row stride (floats)
#define LDBK 136                       // Bt row stride, bf16 ([k][c] layout)
#define LDH 136                        // hsm row stride, bf16

// gemm smem layout (bytes) — all 16B aligned
#define OFF_ASM 0
#define SZ_ASM   (128 * LDA * 2)                // 18432
#define OFF_STG  (OFF_ASM + SZ_ASM)             // 18432
#define SZ_STG   (64 * LDSTG * 4)               // 33792
#define OFF_BT   (OFF_STG + SZ_STG)             // 52224
#define SZ_BT    (64 * LDBK * 2)                // 17408
#define OFF_HSM  (OFF_BT + SZ_BT)               // 69632
#define SZ_HSM   (128 * LDH * 2)                // 34816
#define OFF_HTS0 (OFF_HSM + SZ_HSM)             // 104448 (2 x 512)
#define OFF_RW0  (OFF_HTS0 + 1024)              // 105472 (2 x 256)
#define OFF_RECS0 (OFF_RW0 + 512)               // 105984 (2 x 640)
#define OFF_CNT0  (OFF_RECS0 + 1280)            // 107264 (2 x 512)
#define OFF_HIST0 (OFF_CNT0 + 1024)             // 108288 (2 x 16)
#define OFF_LSB   (OFF_HIST0 + 32)              // 108320 (2048)
#define OFF_LSE   (OFF_LSB + 2048)              // 110368 (512)
#define SMEM_TOTAL (OFF_LSE + 512)              // 110880

// ---- static device scratch (allocation-free rule) ----
// INVARIANT: mutable state zero at start of every launch (module-load zero
// + restore-to-zero in gemm_kernel after each single read).
__device__ __nv_bfloat16 g_lat[NB * NL];
__device__ int g_counts[NG * NB];              // fragment counts, [g][b]
__device__ int g_hist[NBUCKET];
__device__ unsigned short g_recs[NBUCKET * CAP];
__device__ double g_acc;
__device__ unsigned int g_done;

__device__ __forceinline__ void cpasync16(uint32_t dst, const void* src) {
    asm volatile("cp.async.ca.shared.global [%0], [%1], 16;\n"
                 :: "r"(dst), "l"(src));
}
__device__ __forceinline__ void cpasync4(uint32_t dst, const void* src) {
    asm volatile("cp.async.ca.shared.global [%0], [%1], 4;\n"
                 :: "r"(dst), "l"(src));
}
__device__ __forceinline__ void ldsm_x4(uint32_t &r0, uint32_t &r1,
                                        uint32_t &r2, uint32_t &r3, uint32_t addr) {
    asm volatile("ldmatrix.sync.aligned.m8n8.x4.shared.b16 {%0,%1,%2,%3}, [%4];"
                 : "=r"(r0), "=r"(r1), "=r"(r2), "=r"(r3) : "r"(addr));
}
__device__ __forceinline__ void ldsm_x4_t(uint32_t &r0, uint32_t &r1,
                                          uint32_t &r2, uint32_t &r3, uint32_t addr) {
    asm volatile("ldmatrix.sync.aligned.m8n8.x4.trans.shared.b16 {%0,%1,%2,%3}, [%4];"
                 : "=r"(r0), "=r"(r1), "=r"(r2), "=r"(r3) : "r"(addr));
}
__device__ __forceinline__ float ex2f(float x) {
    float r;
    asm("ex2.approx.ftz.f32 %0, %1;" : "=f"(r) : "f"(x));
    return r;
}
__device__ __forceinline__ float lg2f(float x) {
    float r;
    asm("lg2.approx.ftz.f32 %0, %1;" : "=f"(r) : "f"(x));
    return r;
}

// ============================================================
// Kernel 1: fused prep.
//  blocks [0,8): latent -> bf16
//  rest: cut prep (2 cuts/thread): fragment bincount + bucket scatter
// ============================================================
__device__ __forceinline__ void cut_one(int lix, int cxg, float coord) {
    const int lb = lix / NG;
    const int lg = lix - lb * NG;
    atomicAdd(&g_counts[lg * NB + lb], 1);

    const int b = cxg / NG;
    const int g = cxg - b * NG;
    int bin = (int)(coord * 128.0f);
    bin = max(0, min(127, bin));
    const int bucket = g * 2 + (b >> 7);
    const int pos = atomicAdd(&g_hist[bucket], 1);
    if (pos < CAP)
        g_recs[bucket * CAP + pos] = (unsigned short)(((b & 127) << 7) | bin);
}

__global__ __launch_bounds__(256) void prep_kernel(
    const int* __restrict__ local_ix,
    const int* __restrict__ cxg_ix,
    const float* __restrict__ coords,
    const float* __restrict__ latent)
{
    const int tid = threadIdx.x;
    if (blockIdx.x < LAT_BLOCKS) {
        #pragma unroll
        for (int j = 0; j < 8; j++) {
            int idx = blockIdx.x * 2048 + j * 256 + tid;
            g_lat[idx] = __float2bfloat16(latent[idx]);
        }
        return;
    }
    const int base = (blockIdx.x - LAT_BLOCKS) * 256 + tid;
    if (base < CUT_PAIRS) {
        const int2 lix = ((const int2*)local_ix)[base];
        const int2 cxg = ((const int2*)cxg_ix)[base];
        const float2 co = ((const float2*)coords)[base];
        cut_one(lix.x, cxg.x, co.x);
        cut_one(lix.y, cxg.y, co.y);
    }
}

// ============================================================
// Kernel 2: persistent half-gene GEMM pipeline (base-2 logits).
// 296 blocks (2/SM); block = (half, slot); genes g = slot + 148*it.
// Per gene: raw f32 weights cp.async'd into a single-stage buffer one
// gene ahead (with heights/rho/recs/counts/hist double-buffered), then
// converted in-kernel to bf16 [k][c] (x log2e). B fragments via
// ldmatrix.trans. Merged epilogue; Poisson || lg2 finalize; cuts from
// smem; ticketed finalization + restore-to-zero.
// ============================================================
__global__ __launch_bounds__(256, 2) void gemm_kernel(
    const int* __restrict__ genes_oi,
    const float* __restrict__ logit_weight,
    const float* __restrict__ spline_heights,
    const int* __restrict__ cells_oi,
    const float* __restrict__ rho_weight,
    const float* __restrict__ rho_bias,
    const int* __restrict__ libsize,
    float* __restrict__ out)
{
    extern __shared__ char smem_raw[];
    const uint32_t smem_u = (uint32_t)__cvta_generic_to_shared(smem_raw);
    __nv_bfloat16* Asm = (__nv_bfloat16*)(smem_raw + OFF_ASM);
    const float* stg = (const float*)(smem_raw + OFF_STG);
    __nv_bfloat16* btw = (__nv_bfloat16*)(smem_raw + OFF_BT);
    __nv_bfloat16* hsm = (__nv_bfloat16*)(smem_raw + OFF_HSM);
    float* lsebuf = (float*)(smem_raw + OFF_LSB);
    float* lse_sh = (float*)(smem_raw + OFF_LSE);

    const int tid = threadIdx.x;
    const int half = blockIdx.x & 1;
    const int slot = blockIdx.x >> 1;
    const int ngenes = (slot < 76) ? 14 : 13;   // 76*14 + 72*13 = 2000

    // --- load this half's 128 latent rows once ---
    const uint32_t* latw = (const uint32_t*)g_lat + half * 4096;
    uint32_t* asw = (uint32_t*)Asm;
    #pragma unroll
    for (int it = 0; it < 16; it++) {
        int i = tid + it * 256;
        int b = i >> 5, w = i & 31;
        asw[b * (LDA / 2) + w] = latw[i];
    }

    const int warp = tid >> 5, lane = tid & 31;
    const int mw = warp >> 2, nw = warp & 3;
    const int grp = lane >> 2, tig = lane & 3;

    // A fragments: non-trans ldmatrix from [row][k]
    const int rA = (lane & 7) + ((lane >> 3) & 1) * 8;
    const int kA = (lane >> 4) * 8;
    const uint32_t aAddr = smem_u + OFF_ASM
                         + (uint32_t)(((mw * 64 + rA) * LDA + kA) * 2);
    // B fragments: trans ldmatrix from [k][c]
    const int kB = (lane & 7) + ((lane >> 3) & 1) * 8;   // k row
    const int cB = (lane >> 4) * 8;                      // n offset
    const uint32_t bAddr = smem_u + OFF_BT
                         + (uint32_t)((kB * LDBK + nw * 32 + cB) * 2);

    // --- prefetch helper: gene gidx (global id gg); f32 weights into the
    //     single stage buffer; small items into double buffer pb ---
    auto prefetch = [&](int gidx, int gg, int pb) {
        const char* wsrc = (const char*)(logit_weight + (size_t)gg * (NL * NC));
        #pragma unroll
        for (int j = 0; j < 8; j++) {
            int idx = tid + j * 256;          // 2048 x 16B = 32KB
            int r = idx >> 5, ch = idx & 31;
            cpasync16(smem_u + OFF_STG + r * (LDSTG * 4) + ch * 16,
                      wsrc + idx * 16);
        }
        const int t = gidx * 2 + half;
        if (tid < 32)
            cpasync16(smem_u + OFF_HTS0 + pb * 512 + tid * 16,
                      (const char*)(spline_heights + (size_t)gg * NC) + tid * 16);
        else if (tid < 48)
            cpasync16(smem_u + OFF_RW0 + pb * 256 + (tid - 32) * 16,
                      (const char*)(rho_weight + (size_t)gg * NL) + (tid - 32) * 16);
        else if (tid < 88)      // 40 x 16B = 640B = CAP recs
            cpasync16(smem_u + OFF_RECS0 + pb * 640 + (tid - 48) * 16,
                      (const char*)(g_recs + (size_t)t * CAP) + (tid - 48) * 16);
        else if (tid < 120)     // 32 x 16B = 512B = 128 counts
            cpasync16(smem_u + OFF_CNT0 + pb * 512 + (tid - 88) * 16,
                      (const char*)(g_counts + gidx * NB + half * 128) + (tid - 88) * 16);
        else if (tid == 120)
            cpasync4(smem_u + OFF_HIST0 + pb * 16, (const char*)(g_hist + t));
    };

    // --- prologue prefetch: gene 0 ---
    int gg_next = genes_oi[slot];
    prefetch(slot, gg_next, 0);
    asm volatile("cp.async.commit_group;\n");

    float acc = 0.0f;
    int gg_cur;

    for (int it = 0; it < ngenes; it++) {
        const int g = slot + 148 * it;
        const int buf = it & 1;
        gg_cur = gg_next;

        asm volatile("cp.async.wait_group 0;\n");
        __syncthreads();     // stage + small bufs ready; prev-gene hsm reads done

        // --- convert f32 stage -> bf16 Bt [k][c] (x log2e), same layout ---
        {
            const int r = tid >> 2, q = tid & 3;
            const float4* src4 = (const float4*)(stg + r * LDSTG + q * 32);
            uint4* dst4 = (uint4*)(btw + r * LDBK + q * 32);
            #pragma unroll
            for (int j4 = 0; j4 < 4; j4++) {
                uint4 o;
                uint32_t* ow = (uint32_t*)&o;
                #pragma unroll
                for (int p = 0; p < 2; p++) {
                    float4 v = src4[j4 * 2 + p];
                    __nv_bfloat162 b0 = __float22bfloat162_rn(
                        make_float2(v.x * LOG2E, v.y * LOG2E));
                    __nv_bfloat162 b1 = __float22bfloat162_rn(
                        make_float2(v.z * LOG2E, v.w * LOG2E));
                    ow[2 * p] = *(uint32_t*)&b0;
                    ow[2 * p + 1] = *(uint32_t*)&b1;
                }
                dst4[j4] = o;
            }
        }
        __syncthreads();     // Bt ready; stage free for next prefetch

        if (it + 1 < ngenes) {
            const int gn = slot + 148 * (it + 1);
            gg_next = genes_oi[gn];
            prefetch(gn, gg_next, buf ^ 1);
            asm volatile("cp.async.commit_group;\n");
        }

        const float* hts = (const float*)(smem_raw + OFF_HTS0 + buf * 512);
        const float* rw_sh = (const float*)(smem_raw + OFF_RW0 + buf * 256);
        const unsigned short* recs_sh =
            (const unsigned short*)(smem_raw + OFF_RECS0 + buf * 640);
        const int* cnt_sh = (const int*)(smem_raw + OFF_CNT0 + buf * 512);
        const int ncuts = min(*(const int*)(smem_raw + OFF_HIST0 + buf * 16), CAP);
        const int t = g * 2 + half;

        // --- MMA phase ---
        float c[4][4][4];
        #pragma unroll
        for (int mi = 0; mi < 4; mi++)
            #pragma unroll
            for (int nj = 0; nj < 4; nj++)
                #pragma unroll
                for (int q = 0; q < 4; q++) c[mi][nj][q] = 0.0f;

        #pragma unroll
        for (int ki = 0; ki < 4; ki++) {
            uint32_t a[4][4];
            #pragma unroll
            for (int mi = 0; mi < 4; mi++)
                ldsm_x4(a[mi][0], a[mi][1], a[mi][2], a[mi][3],
                        aAddr + mi * (16 * LDA * 2) + ki * 32);
            uint32_t b[4][2];
            #pragma unroll
            for (int p = 0; p < 2; p++)
                ldsm_x4_t(b[2 * p][0], b[2 * p][1], b[2 * p + 1][0], b[2 * p + 1][1],
                          bAddr + ki * (16 * LDBK * 2) + p * 32);
            #pragma unroll
            for (int mi = 0; mi < 4; mi++)
                #pragma unroll
                for (int nj = 0; nj < 4; nj++) {
                    asm volatile(
                        "mma.sync.aligned.m16n8k16.row.col.f32.bf16.bf16.f32 "
                        "{%0,%1,%2,%3}, {%4,%5,%6,%7}, {%8,%9}, {%0,%1,%2,%3};"
                        : "+f"(c[mi][nj][0]), "+f"(c[mi][nj][1]),
                          "+f"(c[mi][nj][2]), "+f"(c[mi][nj][3])
                        : "r"(a[mi][0]), "r"(a[mi][1]), "r"(a[mi][2]), "r"(a[mi][3]),
                          "r"(b[nj][0]), "r"(b[nj][1]));
                }
        }

        // --- Merged epilogue (base-2): h' = c + hts*log2e; store h'; ex2 sums ---
        float2 ht[4];
        #pragma unroll
        for (int nj = 0; nj < 4; nj++) {
            float2 v = *(const float2*)(hts + nw * 32 + 8 * nj + 2 * tig);
            ht[nj] = make_float2(v.x * LOG2E, v.y * LOG2E);
        }

        #pragma unroll
        for (int mi = 0; mi < 4; mi++) {
            const int r0 = mw * 64 + 16 * mi + grp;
            float s0 = 0.0f, s1 = 0.0f;
            #pragma unroll
            for (int nj = 0; nj < 4; nj++) {
                const int col = nw * 32 + 8 * nj + 2 * tig;
                const float h00 = c[mi][nj][0] + ht[nj].x;
                const float h01 = c[mi][nj][1] + ht[nj].y;
                const float h10 = c[mi][nj][2] + ht[nj].x;
                const float h11 = c[mi][nj][3] + ht[nj].y;
                *(__nv_bfloat162*)(hsm + r0 * LDH + col) =
                    __float22bfloat162_rn(make_float2(h00, h01));
                *(__nv_bfloat162*)(hsm + (r0 + 8) * LDH + col) =
                    __float22bfloat162_rn(make_float2(h10, h11));
                s0 += ex2f(h00) + ex2f(h01);
                s1 += ex2f(h10) + ex2f(h11);
            }
            s0 += __shfl_xor_sync(0xffffffffu, s0, 1);
            s0 += __shfl_xor_sync(0xffffffffu, s0, 2);
            s1 += __shfl_xor_sync(0xffffffffu, s1, 1);
            s1 += __shfl_xor_sync(0xffffffffu, s1, 2);
            if (tig == 0) {
                lsebuf[r0 * 4 + nw] = s0;
                lsebuf[(r0 + 8) * 4 + nw] = s1;
            }
        }
        __syncthreads();

        // --- lg2 finalize (tids 0..127) || Poisson (tids 128..255) ---
        if (tid < 128) {
            float tt = lsebuf[tid * 4 + 0] + lsebuf[tid * 4 + 1]
                     + lsebuf[tid * 4 + 2] + lsebuf[tid * 4 + 3];
            lse_sh[tid] = lg2f(tt);
        } else {
            const int r = tid - 128;
            const uint2* ar = (const uint2*)(Asm + r * LDA);
            float rd = 0.0f;
            #pragma unroll
            for (int j = 0; j < 16; j++) {
                uint2 w = ar[j];
                float2 v0 = __bfloat1622float2(*reinterpret_cast<const __nv_bfloat162*>(&w.x));
                float2 v1 = __bfloat1622float2(*reinterpret_cast<const __nv_bfloat162*>(&w.y));
                rd += v0.x * rw_sh[4 * j + 0] + v0.y * rw_sh[4 * j + 1]
                    + v1.x * rw_sh[4 * j + 2] + v1.y * rw_sh[4 * j + 3];
            }
            const int b_glob = half * 128 + r;
            const float rate = rho_bias[gg_cur] * __expf(rd)
                             * (float)libsize[cells_oi[b_glob]];
            const int cnt = cnt_sh[r];
            g_counts[g * NB + b_glob] = 0;          // restore invariant
            float lg = 0.0f;
            for (int k = 2; k <= cnt; k++) lg += __logf((float)k);
            acc += (float)cnt * __logf(rate) - rate - lg;
        }
        __syncthreads();    // hsm + lse_sh ready for cut lookups

        // --- cut likelihood from smem recs: (h' - lse2) * ln2 ---
        {
            for (int j = tid; j < ncuts; j += 256) {
                const unsigned int rec = recs_sh[j];
                const int b_loc = rec >> 7;
                acc += (__bfloat162float(hsm[b_loc * LDH + (rec & 127)])
                        - lse_sh[b_loc]) * LN2;
            }
            if (tid == 0) {
                acc += (float)ncuts * LOG_NBINS;
                g_hist[t] = 0;                      // restore invariant
            }
        }
        // next iteration's top __syncthreads orders hsm/lse_sh reuse
    }

    // --- block reduce + global accumulate + ticketed finalization ---
    {
        __shared__ float sred[8];
        #pragma unroll
        for (int o = 16; o > 0; o >>= 1)
            acc += __shfl_xor_sync(0xffffffffu, acc, o);
        if (lane == 0) sred[warp] = acc;
        __syncthreads();
        if (tid == 0) {
            float tt = 0.0f;
            #pragma unroll
            for (int w = 0; w < 8; w++) tt += sred[w];
            atomicAdd(&g_acc, (double)tt);
            __threadfence();
            unsigned int v = atomicAdd(&g_done, 1u);
            if (v == gridDim.x - 1) {
                __threadfence();
                double a = *((volatile double*)&g_acc);
                out[0] = (float)(-a);
                g_acc = 0.0;
                g_done = 0u;
            }
        }
    }
}

extern "C" void kernel_launch(void* const* d_in, const int* in_sizes, int n_in,
                              void* d_out, int out_size) {
    const float* latent     = (const float*)d_in[0];
    const int*   genes_oi   = (const int*)d_in[1];
    const int*   cells_oi   = (const int*)d_in[2];
    const float* coords     = (const float*)d_in[3];
    const int*   cut_cxg    = (const int*)d_in[4];
    const int*   local_cxg  = (const int*)d_in[6];
    const float* logit_w    = (const float*)d_in[7];
    const float* rho_w      = (const float*)d_in[8];
    const float* rho_b      = (const float*)d_in[9];
    const int*   libsize    = (const int*)d_in[10];
    const float* spline_h   = (const float*)d_in[11];
    float* out = (float*)d_out;

    cudaFuncSetAttribute(gemm_kernel,
                         cudaFuncAttributeMaxDynamicSharedMemorySize, SMEM_TOTAL);

    prep_kernel<<<LAT_BLOCKS + CUT_BLOCKS, 256>>>(local_cxg, cut_cxg,
                                                  coords, latent);
    gemm_kernel<<<NBLK, 256, SMEM_TOTAL>>>(genes_oi, logit_w, spline_h,
                                           cells_oi, rho_w, rho_b, libsize,
                                           out);
}